// round 5
// baseline (speedup 1.0000x reference)
#include <cuda_runtime.h>
#include <cuda_fp16.h>
#include <cstdint>

#define TOK   4096
#define HID   2048
#define INTER 5632

// ---- scratch (device globals; no runtime allocation allowed) ----
__device__ __half g_xh[(size_t)TOK * HID];      // x in fp16
__device__ __half g_wg[(size_t)INTER * HID];    // gate_w fp16
__device__ __half g_wu[(size_t)INTER * HID];    // up_w fp16
__device__ __half g_wd[(size_t)HID * INTER];    // down_w fp16
__device__ __half g_hbuf[(size_t)TOK * INTER];  // hidden activation fp16

// ---- fp32 -> fp16 conversion, vectorized ----
__global__ void convert_f2h(const float* __restrict__ in, __half* __restrict__ out, int n4) {
  int i = blockIdx.x * blockDim.x + threadIdx.x;
  int stride = gridDim.x * blockDim.x;
  for (; i < n4; i += stride) {
    float4 v = reinterpret_cast<const float4*>(in)[i];
    __half2 h0 = __floats2half2_rn(v.x, v.y);
    __half2 h1 = __floats2half2_rn(v.z, v.w);
    reinterpret_cast<__half2*>(out)[2 * i]     = h0;
    reinterpret_cast<__half2*>(out)[2 * i + 1] = h1;
  }
}

// =====================================================================
// helpers: mma.sync / ldmatrix / cp.async  (all valid on plain sm_103)
// =====================================================================
__device__ __forceinline__ uint32_t smem_u32(const void* p) {
  uint32_t a;
  asm("{ .reg .u64 t; cvta.to.shared.u64 t, %1; cvt.u32.u64 %0, t; }" : "=r"(a) : "l"(p));
  return a;
}

__device__ __forceinline__ void mma16816(float* c, const uint32_t* a, const uint32_t* b) {
  asm volatile(
      "mma.sync.aligned.m16n8k16.row.col.f32.f16.f16.f32 "
      "{%0,%1,%2,%3}, {%4,%5,%6,%7}, {%8,%9}, {%0,%1,%2,%3};\n"
      : "+f"(c[0]), "+f"(c[1]), "+f"(c[2]), "+f"(c[3])
      : "r"(a[0]), "r"(a[1]), "r"(a[2]), "r"(a[3]), "r"(b[0]), "r"(b[1]));
}

__device__ __forceinline__ void ldsm4(uint32_t* r, uint32_t addr) {
  asm volatile("ldmatrix.sync.aligned.m8n8.x4.shared.b16 {%0,%1,%2,%3}, [%4];"
               : "=r"(r[0]), "=r"(r[1]), "=r"(r[2]), "=r"(r[3]) : "r"(addr));
}

__device__ __forceinline__ void cp16(uint32_t s, const void* g) {
  asm volatile("cp.async.cg.shared.global [%0], [%1], 16;" :: "r"(s), "l"(g));
}
#define CP_COMMIT() asm volatile("cp.async.commit_group;" ::: "memory")

#define STAGE_B 32768u   // bytes per pipeline stage (both kernels)
#define NSTAGE 3

// Tile geometry: BK = 64 halves = 128 bytes per row -> canonical SW128 swizzle.
// smem byte offset of (row, 16B-chunk c):  row*128 + ((c ^ (row&7)) << 4)

// =====================================================================
// GEMM1 fused gate+up: h = silu(X@Wg^T * gs) * (X@Wu^T * us), fp16 out
// CTA tile: M=128 x N=64 (per weight matrix), BK=64, 3-stage cp.async.
// 8 warps: wm=warp&3 (32 rows), wn=warp>>2 (32 cols); acc 32x32 per matrix.
// stage s at s*32KB: A(16KB) | Bg(8KB) | Bu(8KB)
// =====================================================================
__global__ __launch_bounds__(256, 2)
void gemm1_mma(const __half* __restrict__ X, const __half* __restrict__ Wg,
               const __half* __restrict__ Wu, const float* __restrict__ gs,
               const float* __restrict__ us, __half* __restrict__ Hout) {
  extern __shared__ char smem[];
  const uint32_t sb = smem_u32(smem);
  const int tid = threadIdx.x, lane = tid & 31, warp = tid >> 5;
  const int wm = warp & 3, wn = warp >> 2;       // wn in {0,1}
  const int mBase = blockIdx.y * 128;
  const int nBase = blockIdx.x * 64;
  const int s7 = lane & 7;

  const uint32_t aRow = (uint32_t)((wm * 32 + (lane & 15)) * 128);
  const int hiA = lane >> 4;
  const uint32_t bRow = (uint32_t)((wn * 32 + (lane & 7) + ((lane >> 4) & 1) * 8) * 128);
  const int cB = (lane >> 3) & 1;

  float ag[2][4][4], au[2][4][4];
#pragma unroll
  for (int i = 0; i < 2; i++)
#pragma unroll
    for (int j = 0; j < 4; j++)
#pragma unroll
      for (int k = 0; k < 4; k++) { ag[i][j][k] = 0.f; au[i][j][k] = 0.f; }

  auto load_stage = [&](int kt, int b) {
    const uint32_t base = sb + (uint32_t)b * STAGE_B;
    const int k0 = kt * 64;
#pragma unroll
    for (int i = 0; i < 4; i++) {               // A: 1024 chunks / 256 thr
      int ch = tid + i * 256;
      int row = ch >> 3, c = ch & 7;
      uint32_t sw = (uint32_t)(row * 128 + ((c ^ (row & 7)) << 4));
      cp16(base + sw, X + (size_t)(mBase + row) * HID + k0 + c * 8);
    }
#pragma unroll
    for (int i = 0; i < 2; i++) {               // Bg,Bu: 512 chunks each
      int ch = tid + i * 256;
      int row = ch >> 3, c = ch & 7;
      uint32_t sw = (uint32_t)(row * 128 + ((c ^ (row & 7)) << 4));
      cp16(base + 16384u + sw, Wg + (size_t)(nBase + row) * HID + k0 + c * 8);
      cp16(base + 24576u + sw, Wu + (size_t)(nBase + row) * HID + k0 + c * 8);
    }
    CP_COMMIT();
  };

  const int KT = HID / 64;  // 32
  load_stage(0, 0);
  load_stage(1, 1);

  for (int kt = 0; kt < KT; kt++) {
    if (kt + 1 < KT) asm volatile("cp.async.wait_group 1;" ::: "memory");
    else             asm volatile("cp.async.wait_group 0;" ::: "memory");
    __syncthreads();

    // issue next stage's loads FIRST (into buffer consumed at kt-1)
    if (kt + 2 < KT) load_stage(kt + 2, (kt + 2) % NSTAGE);

    const uint32_t base = sb + (uint32_t)(kt % NSTAGE) * STAGE_B;
    const uint32_t aB = base + aRow;
    const uint32_t gB = base + 16384u + bRow;
    const uint32_t uB = base + 24576u + bRow;
#pragma unroll
    for (int kk = 0; kk < 4; kk++) {
      const uint32_t aOff = (uint32_t)((((kk * 2 + hiA) ^ s7)) << 4);
      uint32_t a[2][4];
      ldsm4(a[0], aB + aOff);
      ldsm4(a[1], aB + 2048u + aOff);
      const uint32_t bOff = (uint32_t)((((kk * 2 + cB) ^ s7)) << 4);
      uint32_t bg[2][4], bu[2][4];
#pragma unroll
      for (int np = 0; np < 2; np++) {
        ldsm4(bg[np], gB + (uint32_t)(np * 2048) + bOff);
        ldsm4(bu[np], uB + (uint32_t)(np * 2048) + bOff);
      }
#pragma unroll
      for (int mt = 0; mt < 2; mt++)
#pragma unroll
        for (int np = 0; np < 2; np++) {
          mma16816(ag[mt][np * 2 + 0], a[mt], &bg[np][0]);
          mma16816(ag[mt][np * 2 + 1], a[mt], &bg[np][2]);
          mma16816(au[mt][np * 2 + 0], a[mt], &bu[np][0]);
          mma16816(au[mt][np * 2 + 1], a[mt], &bu[np][2]);
        }
    }
  }

  // epilogue: dequant + silu-gate, fp16 out
  const int g = lane >> 2, t = lane & 3;
#pragma unroll
  for (int mt = 0; mt < 2; mt++) {
#pragma unroll
    for (int n8 = 0; n8 < 4; n8++) {
      const int col = nBase + wn * 32 + (n8 >> 1) * 16 + (n8 & 1) * 8 + 2 * t;
      const float gs0 = __ldg(gs + col), gs1 = __ldg(gs + col + 1);
      const float us0 = __ldg(us + col), us1 = __ldg(us + col + 1);
      const float* cg = ag[mt][n8];
      const float* cu = au[mt][n8];
      const int r = mBase + wm * 32 + mt * 16 + g;

      float g00 = cg[0] * gs0, g01 = cg[1] * gs1;
      float g10 = cg[2] * gs0, g11 = cg[3] * gs1;
      float u00 = cu[0] * us0, u01 = cu[1] * us1;
      float u10 = cu[2] * us0, u11 = cu[3] * us1;

      float h00 = g00 / (1.f + expf(-g00)) * u00;
      float h01 = g01 / (1.f + expf(-g01)) * u01;
      float h10 = g10 / (1.f + expf(-g10)) * u10;
      float h11 = g11 / (1.f + expf(-g11)) * u11;

      *reinterpret_cast<__half2*>(Hout + (size_t)r * INTER + col) =
          __floats2half2_rn(h00, h01);
      *reinterpret_cast<__half2*>(Hout + (size_t)(r + 8) * INTER + col) =
          __floats2half2_rn(h10, h11);
    }
  }
}

// =====================================================================
// GEMM2: out = (H @ Wd^T) * ds, fp32 out. CTA tile M=128 x N=128, BK=64.
// 8 warps: wm=warp&3 (32 rows), wn=warp>>2 (64 cols); warp 32x64.
// stage s at s*32KB: A(16KB) | B(16KB)
// =====================================================================
__global__ __launch_bounds__(256, 2)
void gemm2_mma(const __half* __restrict__ H, const __half* __restrict__ Wd,
               const float* __restrict__ ds, float* __restrict__ Out) {
  extern __shared__ char smem[];
  const uint32_t sb = smem_u32(smem);
  const int tid = threadIdx.x, lane = tid & 31, warp = tid >> 5;
  const int wm = warp & 3, wn = warp >> 2;
  const int mBase = blockIdx.y * 128;
  const int nBase = blockIdx.x * 128;
  const int s7 = lane & 7;

  const uint32_t aRow = (uint32_t)((wm * 32 + (lane & 15)) * 128);
  const int hiA = lane >> 4;
  const uint32_t bRow = (uint32_t)((wn * 64 + (lane & 7) + ((lane >> 4) & 1) * 8) * 128);
  const int cB = (lane >> 3) & 1;

  float acc[2][8][4];
#pragma unroll
  for (int i = 0; i < 2; i++)
#pragma unroll
    for (int j = 0; j < 8; j++)
#pragma unroll
      for (int k = 0; k < 4; k++) acc[i][j][k] = 0.f;

  auto load_stage = [&](int kt, int b) {
    const uint32_t base = sb + (uint32_t)b * STAGE_B;
    const int k0 = kt * 64;
#pragma unroll
    for (int i = 0; i < 4; i++) {
      int ch = tid + i * 256;
      int row = ch >> 3, c = ch & 7;
      uint32_t sw = (uint32_t)(row * 128 + ((c ^ (row & 7)) << 4));
      cp16(base + sw,          H  + (size_t)(mBase + row) * INTER + k0 + c * 8);
      cp16(base + 16384u + sw, Wd + (size_t)(nBase + row) * INTER + k0 + c * 8);
    }
    CP_COMMIT();
  };

  const int KT = INTER / 64;  // 88
  load_stage(0, 0);
  load_stage(1, 1);

  for (int kt = 0; kt < KT; kt++) {
    if (kt + 1 < KT) asm volatile("cp.async.wait_group 1;" ::: "memory");
    else             asm volatile("cp.async.wait_group 0;" ::: "memory");
    __syncthreads();

    if (kt + 2 < KT) load_stage(kt + 2, (kt + 2) % NSTAGE);

    const uint32_t base = sb + (uint32_t)(kt % NSTAGE) * STAGE_B;
    const uint32_t aB = base + aRow;
    const uint32_t bB = base + 16384u + bRow;
#pragma unroll
    for (int kk = 0; kk < 4; kk++) {
      const uint32_t aOff = (uint32_t)((((kk * 2 + hiA) ^ s7)) << 4);
      uint32_t a[2][4];
      ldsm4(a[0], aB + aOff);
      ldsm4(a[1], aB + 2048u + aOff);
      const uint32_t bOff = (uint32_t)((((kk * 2 + cB) ^ s7)) << 4);
      uint32_t bf[4][4];
#pragma unroll
      for (int np = 0; np < 4; np++)
        ldsm4(bf[np], bB + (uint32_t)(np * 2048) + bOff);
#pragma unroll
      for (int mt = 0; mt < 2; mt++)
#pragma unroll
        for (int np = 0; np < 4; np++) {
          mma16816(acc[mt][np * 2 + 0], a[mt], &bf[np][0]);
          mma16816(acc[mt][np * 2 + 1], a[mt], &bf[np][2]);
        }
    }
  }

  const int g = lane >> 2, t = lane & 3;
#pragma unroll
  for (int mt = 0; mt < 2; mt++) {
#pragma unroll
    for (int n8 = 0; n8 < 8; n8++) {
      const int col = nBase + wn * 64 + (n8 >> 1) * 16 + (n8 & 1) * 8 + 2 * t;
      const float d0 = __ldg(ds + col), d1 = __ldg(ds + col + 1);
      const float* cc = acc[mt][n8];
      const int r = mBase + wm * 32 + mt * 16 + g;
      *reinterpret_cast<float2*>(Out + (size_t)r * HID + col) =
          make_float2(cc[0] * d0, cc[1] * d1);
      *reinterpret_cast<float2*>(Out + (size_t)(r + 8) * HID + col) =
          make_float2(cc[2] * d0, cc[3] * d1);
    }
  }
}

// =====================================================================
extern "C" void kernel_launch(void* const* d_in, const int* in_sizes, int n_in,
                              void* d_out, int out_size) {
  const float* x      = (const float*)d_in[0];
  const float* gate_w = (const float*)d_in[1];
  const float* up_w   = (const float*)d_in[2];
  const float* down_w = (const float*)d_in[3];
  const float* gate_s = (const float*)d_in[4];
  const float* up_s   = (const float*)d_in[5];
  const float* down_s = (const float*)d_in[6];
  float* out = (float*)d_out;

  __half *xh, *wg, *wu, *wd, *hb;
  cudaGetSymbolAddress((void**)&xh, g_xh);
  cudaGetSymbolAddress((void**)&wg, g_wg);
  cudaGetSymbolAddress((void**)&wu, g_wu);
  cudaGetSymbolAddress((void**)&wd, g_wd);
  cudaGetSymbolAddress((void**)&hb, g_hbuf);

  const int SMEM = NSTAGE * (int)STAGE_B;  // 98304: 2 CTAs/SM (192KB/228KB)
  cudaFuncSetAttribute(gemm1_mma, cudaFuncAttributeMaxDynamicSharedMemorySize, SMEM);
  cudaFuncSetAttribute(gemm2_mma, cudaFuncAttributeMaxDynamicSharedMemorySize, SMEM);

  const int n4x = (TOK * HID) / 4;
  const int n4w = (INTER * HID) / 4;
  convert_f2h<<<2048, 256>>>(x, xh, n4x);
  convert_f2h<<<2048, 256>>>(gate_w, wg, n4w);
  convert_f2h<<<2048, 256>>>(up_w, wu, n4w);
  convert_f2h<<<2048, 256>>>(down_w, wd, n4w);

  dim3 grid1(INTER / 64, TOK / 128);   // (88, 32)
  gemm1_mma<<<grid1, 256, SMEM>>>(xh, wg, wu, gate_s, up_s, hb);

  dim3 grid2(HID / 128, TOK / 128);    // (16, 32)
  gemm2_mma<<<grid2, 256, SMEM>>>(hb, wd, down_s, out);
}